// round 6
// baseline (speedup 1.0000x reference)
#include <cuda_runtime.h>
#include <cuda_fp16.h>
#include <cstdint>

#define FEAT 128
#define BM 128
#define BN 128
#define BK 16
#define PAD_BM 132   // pad: row stride 528B (16B-aligned, conflict-reducing)

typedef unsigned long long ull;

// scratch for v @ Wvn in fp16  (N padded to 50176 rows)
__device__ __half g_vWn_h[50176 * FEAT];

// ---------------------------------------------------------------------------
// Packed dual-fp32 FMA (Blackwell family-wide, SASS FFMA2).
// ---------------------------------------------------------------------------
__device__ __forceinline__ unsigned long long pack2(float x, float y) {
    unsigned long long r;
    asm("mov.b64 %0, {%1, %2};" : "=l"(r) : "f"(x), "f"(y));
    return r;
}
__device__ __forceinline__ float2 unpack2(unsigned long long v) {
    float2 f;
    asm("mov.b64 {%0, %1}, %2;" : "=f"(f.x), "=f"(f.y) : "l"(v));
    return f;
}
__device__ __forceinline__ void ffma2(unsigned long long& acc,
                                      unsigned long long a,
                                      unsigned long long b) {
    asm("fma.rn.f32x2 %0, %1, %2, %0;" : "+l"(acc) : "l"(a), "l"(b));
}

// ---------------------------------------------------------------------------
// Kernel 1: C = A[n,128] @ W[128,128].  blockIdx.y==0 -> Wvc, out=d_out (fp32)
//                                       blockIdx.y==1 -> Wvn, out=g_vWn_h (fp16)
// 128x128 tile, 256 threads, 8x8 per-thread tile.
// FFMA2 inner loop with ZERO packing movs:
//   - acc lanes = row pairs; A pairs come directly from transposed As via LDS.128
//   - B stored DUPLICATED in smem so broadcast pairs come directly via LDS.128
// ---------------------------------------------------------------------------
__global__ __launch_bounds__(256) void gemm_kernel(
    const float* __restrict__ A,
    const float* __restrict__ Wvc,
    const float* __restrict__ Wvn,
    float* __restrict__ outZc,
    int n)
{
    __shared__ float As[BK][PAD_BM];     // transposed A tile: As[k][m]
    __shared__ float Bs2[BK][2 * BN];    // duplicated W tile: Bs2[k][2j]=Bs2[k][2j+1]=W[k][j]

    const bool isZc = (blockIdx.y == 0);
    const float* W = isZc ? Wvc : Wvn;

    int tid = threadIdx.x;
    int tx = tid & 15;     // 0..15 -> column group
    int ty = tid >> 4;     // 0..15 -> row group
    int blockRow = blockIdx.x * BM;

    // acc2[p][c]: p = row-pair (0: rows ty*4+0/1, 1: +2/3, 2: 64+ty*4+0/1, 3: +2/3)
    //             c = column  (0..3: tx*4+c, 4..7: 64+tx*4+(c-4))
    ull acc2[4][8];
    #pragma unroll
    for (int p = 0; p < 4; p++)
        #pragma unroll
        for (int c = 0; c < 8; c++)
            acc2[p][c] = 0ull;

    for (int k0 = 0; k0 < FEAT; k0 += BK) {
        // ---- load A tile (128 rows x 16 k) transposed into As ----
        #pragma unroll
        for (int i = 0; i < 2; i++) {
            int f4  = tid + i * 256;   // 0..511
            int row = f4 >> 2;         // 0..127
            int q   = f4 & 3;          // which float4 in the 16-wide k chunk
            int grow = blockRow + row;
            float4 v = make_float4(0.f, 0.f, 0.f, 0.f);
            if (grow < n)
                v = reinterpret_cast<const float4*>(A)[grow * (FEAT / 4) + (k0 >> 2) + q];
            As[4 * q + 0][row] = v.x;
            As[4 * q + 1][row] = v.y;
            As[4 * q + 2][row] = v.z;
            As[4 * q + 3][row] = v.w;
        }
        // ---- load W tile (16 k x 128 cols), duplicated ----
        #pragma unroll
        for (int i = 0; i < 2; i++) {
            int f4 = tid + i * 256;    // 0..511
            int kk = f4 >> 5;          // 0..15
            int c4 = f4 & 31;          // 0..31 float4 columns
            float4 w = reinterpret_cast<const float4*>(W)[(k0 + kk) * (FEAT / 4) + c4];
            float4* dst = reinterpret_cast<float4*>(&Bs2[kk][c4 * 8]);
            dst[0] = make_float4(w.x, w.x, w.y, w.y);
            dst[1] = make_float4(w.z, w.z, w.w, w.w);
        }
        __syncthreads();

        // ---- compute: 6 LDS.128 + 32 FFMA2 per kk, no packing ----
        #pragma unroll
        for (int kk = 0; kk < BK; kk++) {
            ulonglong2 a0 = *reinterpret_cast<const ulonglong2*>(&As[kk][ty * 4]);
            ulonglong2 a1 = *reinterpret_cast<const ulonglong2*>(&As[kk][64 + ty * 4]);
            ulonglong2 b0 = *reinterpret_cast<const ulonglong2*>(&Bs2[kk][tx * 8]);
            ulonglong2 b1 = *reinterpret_cast<const ulonglong2*>(&Bs2[kk][tx * 8 + 4]);
            ulonglong2 b2 = *reinterpret_cast<const ulonglong2*>(&Bs2[kk][128 + tx * 8]);
            ulonglong2 b3 = *reinterpret_cast<const ulonglong2*>(&Bs2[kk][128 + tx * 8 + 4]);
            ull ap[4] = {a0.x, a0.y, a1.x, a1.y};
            ull bp[8] = {b0.x, b0.y, b1.x, b1.y, b2.x, b2.y, b3.x, b3.y};
            #pragma unroll
            for (int p = 0; p < 4; p++)
                #pragma unroll
                for (int c = 0; c < 8; c++)
                    ffma2(acc2[p][c], ap[p], bp[c]);
        }
        __syncthreads();
    }

    // ---- store: unpack row pairs ----
    #pragma unroll
    for (int p = 0; p < 4; p++) {
        float2 u[8];
        #pragma unroll
        for (int c = 0; c < 8; c++) u[c] = unpack2(acc2[p][c]);
        int rbase = (p < 2) ? (ty * 4 + 2 * p) : (64 + ty * 4 + 2 * (p - 2));
        #pragma unroll
        for (int l = 0; l < 2; l++) {
            int grow = blockRow + rbase + l;
            if (grow >= n) continue;
            float f[8];
            #pragma unroll
            for (int c = 0; c < 8; c++) f[c] = l ? u[c].y : u[c].x;
            if (isZc) {
                float4* o = reinterpret_cast<float4*>(outZc + (size_t)grow * FEAT);
                o[tx]      = make_float4(f[0], f[1], f[2], f[3]);
                o[16 + tx] = make_float4(f[4], f[5], f[6], f[7]);
            } else {
                __half2* o = reinterpret_cast<__half2*>(g_vWn_h + (size_t)grow * FEAT);
                o[tx * 2 + 0]      = __floats2half2_rn(f[0], f[1]);
                o[tx * 2 + 1]      = __floats2half2_rn(f[2], f[3]);
                o[32 + tx * 2 + 0] = __floats2half2_rn(f[4], f[5]);
                o[32 + tx * 2 + 1] = __floats2half2_rn(f[6], f[7]);
            }
        }
    }
}

// ---------------------------------------------------------------------------
// Kernel 2: per-row neighbor gather + epilogue (unchanged from R5).
// ---------------------------------------------------------------------------
__global__ __launch_bounds__(256, 4) void gather_kernel(
    float* __restrict__ out,
    const int* __restrict__ nh_idx,
    const int* __restrict__ int_idx,
    const float* __restrict__ nh_e,
    const float* __restrict__ int_e,
    const float* __restrict__ bv,
    int n)
{
    int gwarp = (blockIdx.x * blockDim.x + threadIdx.x) >> 5;
    int lane  = threadIdx.x & 31;
    if (gwarp >= n) return;
    int row = gwarp;

    const uint2* vW2 = reinterpret_cast<const uint2*>(g_vWn_h);

    int   idxs[40];
    float es[40];
    {
        const int4*   ni4 = reinterpret_cast<const int4*>(nh_idx  + row * 20);
        const int4*   ii4 = reinterpret_cast<const int4*>(int_idx + row * 20);
        const float4* ne4 = reinterpret_cast<const float4*>(nh_e  + row * 20);
        const float4* ie4 = reinterpret_cast<const float4*>(int_e + row * 20);
        #pragma unroll
        for (int q = 0; q < 5; q++) {
            int4   a = __ldg(ni4 + q);
            float4 e = __ldg(ne4 + q);
            idxs[4*q+0] = a.x; idxs[4*q+1] = a.y; idxs[4*q+2] = a.z; idxs[4*q+3] = a.w;
            es[4*q+0] = e.x; es[4*q+1] = e.y; es[4*q+2] = e.z; es[4*q+3] = e.w;
        }
        #pragma unroll
        for (int q = 0; q < 5; q++) {
            int4   a = __ldg(ii4 + q);
            float4 e = __ldg(ie4 + q);
            idxs[20+4*q+0] = a.x; idxs[20+4*q+1] = a.y; idxs[20+4*q+2] = a.z; idxs[20+4*q+3] = a.w;
            es[20+4*q+0] = e.x; es[20+4*q+1] = e.y; es[20+4*q+2] = e.z; es[20+4*q+3] = e.w;
        }
    }

    int cnt = 0;
    #pragma unroll
    for (int j = 0; j < 40; j++) {
        bool v = idxs[j] >= 0;
        cnt += v ? 1 : 0;
        es[j]   = v ? es[j] : 0.0f;
        idxs[j] = v ? idxs[j] : 0;
    }

    // unconditional fp16 gathers, packed f32x2 accumulate (two chains)
    unsigned long long accA0 = 0ull, accB0 = 0ull;
    unsigned long long accA1 = 0ull, accB1 = 0ull;
    #pragma unroll
    for (int j = 0; j < 40; j += 2) {
        uint2 r0 = __ldg(vW2 + (size_t)idxs[j]   * 32 + lane);
        uint2 r1 = __ldg(vW2 + (size_t)idxs[j+1] * 32 + lane);
        float2 v0a = __half22float2(*reinterpret_cast<__half2*>(&r0.x));
        float2 v0b = __half22float2(*reinterpret_cast<__half2*>(&r0.y));
        float2 v1a = __half22float2(*reinterpret_cast<__half2*>(&r1.x));
        float2 v1b = __half22float2(*reinterpret_cast<__half2*>(&r1.y));
        unsigned long long e0 = pack2(es[j],   es[j]);
        unsigned long long e1 = pack2(es[j+1], es[j+1]);
        ffma2(accA0, e0, pack2(v0a.x, v0a.y));
        ffma2(accB0, e0, pack2(v0b.x, v0b.y));
        ffma2(accA1, e1, pack2(v1a.x, v1a.y));
        ffma2(accB1, e1, pack2(v1b.x, v1b.y));
    }
    float2 a0 = unpack2(accA0), a1 = unpack2(accA1);
    float2 b0f = unpack2(accB0), b1f = unpack2(accB1);
    float4 acc = make_float4(a0.x + a1.x, a0.y + a1.y,
                             b0f.x + b1f.x, b0f.y + b1f.y);

    float inv = 1.0f / (float)cnt;
    float4 zc = reinterpret_cast<const float4*>(out)[(size_t)row * 32 + lane];
    float4 b  = __ldg(reinterpret_cast<const float4*>(bv) + lane);
    float4 z;
    z.x = fmaxf(fmaf(acc.x, inv, zc.x) + b.x, 0.f);
    z.y = fmaxf(fmaf(acc.y, inv, zc.y) + b.y, 0.f);
    z.z = fmaxf(fmaf(acc.z, inv, zc.z) + b.z, 0.f);
    z.w = fmaxf(fmaf(acc.w, inv, zc.w) + b.w, 0.f);
    reinterpret_cast<float4*>(out)[(size_t)row * 32 + lane] = z;
}

// ---------------------------------------------------------------------------
extern "C" void kernel_launch(void* const* d_in, const int* in_sizes, int n_in,
                              void* d_out, int out_size) {
    const float* vertices    = (const float*)d_in[0];
    const int*   nh_indices  = (const int*)  d_in[1];
    const int*   int_indices = (const int*)  d_in[2];
    const float* nh_edges    = (const float*)d_in[3];
    const float* int_edges   = (const float*)d_in[4];
    const float* Wvc         = (const float*)d_in[5];
    const float* Wvn         = (const float*)d_in[6];
    const float* bv          = (const float*)d_in[7];
    float* out = (float*)d_out;

    int n = in_sizes[0] / FEAT;   // 50000

    dim3 g1((n + BM - 1) / BM, 2);
    gemm_kernel<<<g1, 256>>>(vertices, Wvc, Wvn, out, n);

    int warps_per_block = 256 / 32;
    int g2 = (n + warps_per_block - 1) / warps_per_block;
    gather_kernel<<<g2, 256>>>(out, nh_indices, int_indices, nh_edges, int_edges, bv, n);
}

// round 7
// speedup vs baseline: 1.3622x; 1.3622x over previous
#include <cuda_runtime.h>
#include <cuda_fp16.h>
#include <cstdint>

#define FEAT 128
#define BM 128
#define BN 128
#define BK 16
#define PAD_A2 260   // duplicated-A row stride in floats (1040B: 16B-aligned)

typedef unsigned long long ull;

// scratch for v @ Wvn in fp16  (N padded to 50176 rows)
__device__ __half g_vWn_h[50176 * FEAT];

// ---------------------------------------------------------------------------
// Packed dual-fp32 FMA (Blackwell family-wide, SASS FFMA2).
// ---------------------------------------------------------------------------
__device__ __forceinline__ unsigned long long pack2(float x, float y) {
    unsigned long long r;
    asm("mov.b64 %0, {%1, %2};" : "=l"(r) : "f"(x), "f"(y));
    return r;
}
__device__ __forceinline__ float2 unpack2(unsigned long long v) {
    float2 f;
    asm("mov.b64 {%0, %1}, %2;" : "=f"(f.x), "=f"(f.y) : "l"(v));
    return f;
}
__device__ __forceinline__ void ffma2(unsigned long long& acc,
                                      unsigned long long a,
                                      unsigned long long b) {
    asm("fma.rn.f32x2 %0, %1, %2, %0;" : "+l"(acc) : "l"(a), "l"(b));
}

// ---------------------------------------------------------------------------
// Kernel 1: C = A[n,128] @ W[128,128].  blockIdx.y==0 -> Wvc, out=d_out (fp32)
//                                       blockIdx.y==1 -> Wvn, out=g_vWn_h (fp16)
// 128x128 tile, 256 threads, 8x8 per-thread tile, FFMA2 inner loop.
//   - A stored transposed AND duplicated: As2[k][2m]=As2[k][2m+1]=A[row m].
//     Broadcast pairs come from LDS.128 (2 distinct addrs/warp -> broadcast).
//   - B kept in R5 layout; packed col-pairs are direct ulonglong2 reloads.
//   - 6 LDS.128 + 32 FFMA2 per kk, zero packing movs.
// ---------------------------------------------------------------------------
__global__ __launch_bounds__(256) void gemm_kernel(
    const float* __restrict__ A,
    const float* __restrict__ Wvc,
    const float* __restrict__ Wvn,
    float* __restrict__ outZc,
    int n)
{
    __shared__ float As2[BK][PAD_A2];   // transposed+duplicated A: As2[k][2m],[2m+1]
    __shared__ float Bs[BK][BN];        // W tile: Bs[k][ncol]

    const bool isZc = (blockIdx.y == 0);
    const float* W = isZc ? Wvc : Wvn;

    int tid = threadIdx.x;
    int tx = tid & 15;     // 0..15 -> column group
    int ty = tid >> 4;     // 0..15 -> row group
    int blockRow = blockIdx.x * BM;

    // acc2[i][j]: row i (0..3: ty*4+i, 4..7: 64+ty*4+(i-4)) x col-pair j
    //             (j=0..1: cols tx*4 + 2j..2j+1, j=2..3: cols 64+tx*4+...)
    ull acc2[8][4];
    #pragma unroll
    for (int i = 0; i < 8; i++)
        #pragma unroll
        for (int j = 0; j < 4; j++)
            acc2[i][j] = 0ull;

    for (int k0 = 0; k0 < FEAT; k0 += BK) {
        // ---- load A tile (128 rows x 16 k) transposed+duplicated into As2 ----
        #pragma unroll
        for (int i = 0; i < 2; i++) {
            int f4  = tid + i * 256;   // 0..511
            int row = f4 >> 2;         // 0..127
            int q   = f4 & 3;          // which float4 in the 16-wide k chunk
            int grow = blockRow + row;
            float4 v = make_float4(0.f, 0.f, 0.f, 0.f);
            if (grow < n)
                v = reinterpret_cast<const float4*>(A)[grow * (FEAT / 4) + (k0 >> 2) + q];
            *reinterpret_cast<float2*>(&As2[4 * q + 0][2 * row]) = make_float2(v.x, v.x);
            *reinterpret_cast<float2*>(&As2[4 * q + 1][2 * row]) = make_float2(v.y, v.y);
            *reinterpret_cast<float2*>(&As2[4 * q + 2][2 * row]) = make_float2(v.z, v.z);
            *reinterpret_cast<float2*>(&As2[4 * q + 3][2 * row]) = make_float2(v.w, v.w);
        }
        // ---- load W tile (16 k x 128 cols) ----
        #pragma unroll
        for (int i = 0; i < 2; i++) {
            int f4 = tid + i * 256;    // 0..511
            int kk = f4 >> 5;          // 0..15
            int c4 = f4 & 31;          // 0..31 float4 columns
            reinterpret_cast<float4*>(&Bs[kk][0])[c4] =
                reinterpret_cast<const float4*>(W)[(k0 + kk) * (FEAT / 4) + c4];
        }
        __syncthreads();

        // ---- compute: 6 LDS.128 + 32 FFMA2 per kk, no packing movs ----
        #pragma unroll
        for (int kk = 0; kk < BK; kk++) {
            // A broadcast pairs (duplicated rows): rows ty*4.. and 64+ty*4..
            ulonglong2 a01 = *reinterpret_cast<const ulonglong2*>(&As2[kk][ty * 8]);
            ulonglong2 a23 = *reinterpret_cast<const ulonglong2*>(&As2[kk][ty * 8 + 4]);
            ulonglong2 a45 = *reinterpret_cast<const ulonglong2*>(&As2[kk][128 + ty * 8]);
            ulonglong2 a67 = *reinterpret_cast<const ulonglong2*>(&As2[kk][128 + ty * 8 + 4]);
            // B packed col-pairs, straight from LDS.128
            ulonglong2 b0 = *reinterpret_cast<const ulonglong2*>(&Bs[kk][tx * 4]);
            ulonglong2 b1 = *reinterpret_cast<const ulonglong2*>(&Bs[kk][64 + tx * 4]);
            ull ap[8] = {a01.x, a01.y, a23.x, a23.y, a45.x, a45.y, a67.x, a67.y};
            ull bp[4] = {b0.x, b0.y, b1.x, b1.y};
            #pragma unroll
            for (int i = 0; i < 8; i++)
                #pragma unroll
                for (int j = 0; j < 4; j++)
                    ffma2(acc2[i][j], ap[i], bp[j]);
        }
        __syncthreads();
    }

    // ---- store ----
    #pragma unroll
    for (int i = 0; i < 8; i++) {
        int r = (i < 4) ? (ty * 4 + i) : (64 + ty * 4 + (i - 4));
        int grow = blockRow + r;
        if (grow >= n) continue;
        float2 p0 = unpack2(acc2[i][0]);
        float2 p1 = unpack2(acc2[i][1]);
        float2 p2 = unpack2(acc2[i][2]);
        float2 p3 = unpack2(acc2[i][3]);
        if (isZc) {
            float4* o = reinterpret_cast<float4*>(outZc + (size_t)grow * FEAT);
            o[tx]      = make_float4(p0.x, p0.y, p1.x, p1.y);
            o[16 + tx] = make_float4(p2.x, p2.y, p3.x, p3.y);
        } else {
            __half2* o = reinterpret_cast<__half2*>(g_vWn_h + (size_t)grow * FEAT);
            o[tx * 2 + 0]      = __floats2half2_rn(p0.x, p0.y);
            o[tx * 2 + 1]      = __floats2half2_rn(p1.x, p1.y);
            o[32 + tx * 2 + 0] = __floats2half2_rn(p2.x, p2.y);
            o[32 + tx * 2 + 1] = __floats2half2_rn(p3.x, p3.y);
        }
    }
}

// ---------------------------------------------------------------------------
// Kernel 2: per-row neighbor gather + epilogue (unchanged from R5).
// ---------------------------------------------------------------------------
__global__ __launch_bounds__(256, 4) void gather_kernel(
    float* __restrict__ out,
    const int* __restrict__ nh_idx,
    const int* __restrict__ int_idx,
    const float* __restrict__ nh_e,
    const float* __restrict__ int_e,
    const float* __restrict__ bv,
    int n)
{
    int gwarp = (blockIdx.x * blockDim.x + threadIdx.x) >> 5;
    int lane  = threadIdx.x & 31;
    if (gwarp >= n) return;
    int row = gwarp;

    const uint2* vW2 = reinterpret_cast<const uint2*>(g_vWn_h);

    int   idxs[40];
    float es[40];
    {
        const int4*   ni4 = reinterpret_cast<const int4*>(nh_idx  + row * 20);
        const int4*   ii4 = reinterpret_cast<const int4*>(int_idx + row * 20);
        const float4* ne4 = reinterpret_cast<const float4*>(nh_e  + row * 20);
        const float4* ie4 = reinterpret_cast<const float4*>(int_e + row * 20);
        #pragma unroll
        for (int q = 0; q < 5; q++) {
            int4   a = __ldg(ni4 + q);
            float4 e = __ldg(ne4 + q);
            idxs[4*q+0] = a.x; idxs[4*q+1] = a.y; idxs[4*q+2] = a.z; idxs[4*q+3] = a.w;
            es[4*q+0] = e.x; es[4*q+1] = e.y; es[4*q+2] = e.z; es[4*q+3] = e.w;
        }
        #pragma unroll
        for (int q = 0; q < 5; q++) {
            int4   a = __ldg(ii4 + q);
            float4 e = __ldg(ie4 + q);
            idxs[20+4*q+0] = a.x; idxs[20+4*q+1] = a.y; idxs[20+4*q+2] = a.z; idxs[20+4*q+3] = a.w;
            es[20+4*q+0] = e.x; es[20+4*q+1] = e.y; es[20+4*q+2] = e.z; es[20+4*q+3] = e.w;
        }
    }

    int cnt = 0;
    #pragma unroll
    for (int j = 0; j < 40; j++) {
        bool v = idxs[j] >= 0;
        cnt += v ? 1 : 0;
        es[j]   = v ? es[j] : 0.0f;
        idxs[j] = v ? idxs[j] : 0;
    }

    // unconditional fp16 gathers, packed f32x2 accumulate (two chains)
    unsigned long long accA0 = 0ull, accB0 = 0ull;
    unsigned long long accA1 = 0ull, accB1 = 0ull;
    #pragma unroll
    for (int j = 0; j < 40; j += 2) {
        uint2 r0 = __ldg(vW2 + (size_t)idxs[j]   * 32 + lane);
        uint2 r1 = __ldg(vW2 + (size_t)idxs[j+1] * 32 + lane);
        float2 v0a = __half22float2(*reinterpret_cast<__half2*>(&r0.x));
        float2 v0b = __half22float2(*reinterpret_cast<__half2*>(&r0.y));
        float2 v1a = __half22float2(*reinterpret_cast<__half2*>(&r1.x));
        float2 v1b = __half22float2(*reinterpret_cast<__half2*>(&r1.y));
        unsigned long long e0 = pack2(es[j],   es[j]);
        unsigned long long e1 = pack2(es[j+1], es[j+1]);
        ffma2(accA0, e0, pack2(v0a.x, v0a.y));
        ffma2(accB0, e0, pack2(v0b.x, v0b.y));
        ffma2(accA1, e1, pack2(v1a.x, v1a.y));
        ffma2(accB1, e1, pack2(v1b.x, v1b.y));
    }
    float2 a0 = unpack2(accA0), a1 = unpack2(accA1);
    float2 b0f = unpack2(accB0), b1f = unpack2(accB1);
    float4 acc = make_float4(a0.x + a1.x, a0.y + a1.y,
                             b0f.x + b1f.x, b0f.y + b1f.y);

    float inv = 1.0f / (float)cnt;
    float4 zc = reinterpret_cast<const float4*>(out)[(size_t)row * 32 + lane];
    float4 b  = __ldg(reinterpret_cast<const float4*>(bv) + lane);
    float4 z;
    z.x = fmaxf(fmaf(acc.x, inv, zc.x) + b.x, 0.f);
    z.y = fmaxf(fmaf(acc.y, inv, zc.y) + b.y, 0.f);
    z.z = fmaxf(fmaf(acc.z, inv, zc.z) + b.z, 0.f);
    z.w = fmaxf(fmaf(acc.w, inv, zc.w) + b.w, 0.f);
    reinterpret_cast<float4*>(out)[(size_t)row * 32 + lane] = z;
}

// ---------------------------------------------------------------------------
extern "C" void kernel_launch(void* const* d_in, const int* in_sizes, int n_in,
                              void* d_out, int out_size) {
    const float* vertices    = (const float*)d_in[0];
    const int*   nh_indices  = (const int*)  d_in[1];
    const int*   int_indices = (const int*)  d_in[2];
    const float* nh_edges    = (const float*)d_in[3];
    const float* int_edges   = (const float*)d_in[4];
    const float* Wvc         = (const float*)d_in[5];
    const float* Wvn         = (const float*)d_in[6];
    const float* bv          = (const float*)d_in[7];
    float* out = (float*)d_out;

    int n = in_sizes[0] / FEAT;   // 50000

    dim3 g1((n + BM - 1) / BM, 2);
    gemm_kernel<<<g1, 256>>>(vertices, Wvc, Wvn, out, n);

    int warps_per_block = 256 / 32;
    int g2 = (n + warps_per_block - 1) / warps_per_block;
    gather_kernel<<<g2, 256>>>(out, nh_indices, int_indices, nh_edges, int_edges, bv, n);
}

// round 8
// speedup vs baseline: 1.4760x; 1.0835x over previous
#include <cuda_runtime.h>
#include <cuda_fp16.h>
#include <cstdint>

#define FEAT 128
#define BM 128
#define BN 128
#define BK 16
#define PAD_BM 132   // pad to reduce transposed-store bank conflicts

typedef unsigned long long ull;

// scratch for v @ Wvn in fp16  (N padded to 50176 rows)
__device__ __half g_vWn_h[50176 * FEAT];
// prepped neighbor data: per row 40 x idx (uint32) + 40 x half2(e/cnt, e/cnt)
__device__ uint32_t g_prep[50176 * 80];

// ---------------------------------------------------------------------------
// Packed dual-fp32 FMA (Blackwell family-wide, SASS FFMA2).
// ---------------------------------------------------------------------------
__device__ __forceinline__ unsigned long long pack2(float x, float y) {
    unsigned long long r;
    asm("mov.b64 %0, {%1, %2};" : "=l"(r) : "f"(x), "f"(y));
    return r;
}
__device__ __forceinline__ float2 unpack2(unsigned long long v) {
    float2 f;
    asm("mov.b64 {%0, %1}, %2;" : "=f"(f.x), "=f"(f.y) : "l"(v));
    return f;
}
__device__ __forceinline__ void ffma2(unsigned long long& acc,
                                      unsigned long long a,
                                      unsigned long long b) {
    asm("fma.rn.f32x2 %0, %1, %2, %0;" : "+l"(acc) : "l"(a), "l"(b));
}

// ---------------------------------------------------------------------------
// Kernel 1: GEMM (verbatim R5 version — measured 67us for both outputs).
// ---------------------------------------------------------------------------
__global__ __launch_bounds__(256) void gemm_kernel(
    const float* __restrict__ A,
    const float* __restrict__ Wvc,
    const float* __restrict__ Wvn,
    float* __restrict__ outZc,
    int n)
{
    __shared__ float As[BK][PAD_BM];   // transposed A tile: As[k][m]
    __shared__ float Bs[BK][BN];       // W tile: Bs[k][ncol]

    const bool isZc = (blockIdx.y == 0);
    const float* W = isZc ? Wvc : Wvn;

    int tid = threadIdx.x;
    int tx = tid & 15;     // 0..15 -> column group
    int ty = tid >> 4;     // 0..15 -> row group
    int blockRow = blockIdx.x * BM;

    ull acc2[8][4];
    #pragma unroll
    for (int i = 0; i < 8; i++)
        #pragma unroll
        for (int j = 0; j < 4; j++)
            acc2[i][j] = 0ull;

    for (int k0 = 0; k0 < FEAT; k0 += BK) {
        #pragma unroll
        for (int i = 0; i < 2; i++) {
            int f4  = tid + i * 256;
            int row = f4 >> 2;
            int q   = f4 & 3;
            int grow = blockRow + row;
            float4 v = make_float4(0.f, 0.f, 0.f, 0.f);
            if (grow < n)
                v = reinterpret_cast<const float4*>(A)[grow * (FEAT / 4) + (k0 >> 2) + q];
            As[4 * q + 0][row] = v.x;
            As[4 * q + 1][row] = v.y;
            As[4 * q + 2][row] = v.z;
            As[4 * q + 3][row] = v.w;
        }
        #pragma unroll
        for (int i = 0; i < 2; i++) {
            int f4 = tid + i * 256;
            int kk = f4 >> 5;
            int c4 = f4 & 31;
            reinterpret_cast<float4*>(&Bs[kk][0])[c4] =
                reinterpret_cast<const float4*>(W)[(k0 + kk) * (FEAT / 4) + c4];
        }
        __syncthreads();

        #pragma unroll
        for (int kk = 0; kk < BK; kk++) {
            float4 a0 = *reinterpret_cast<const float4*>(&As[kk][ty * 4]);
            float4 a1 = *reinterpret_cast<const float4*>(&As[kk][64 + ty * 4]);
            float4 b0 = *reinterpret_cast<const float4*>(&Bs[kk][tx * 4]);
            float4 b1 = *reinterpret_cast<const float4*>(&Bs[kk][64 + tx * 4]);

            ull bp[4] = {
                pack2(b0.x, b0.y), pack2(b0.z, b0.w),
                pack2(b1.x, b1.y), pack2(b1.z, b1.w)
            };
            float a[8] = {a0.x, a0.y, a0.z, a0.w, a1.x, a1.y, a1.z, a1.w};
            #pragma unroll
            for (int i = 0; i < 8; i++) {
                ull ap = pack2(a[i], a[i]);
                #pragma unroll
                for (int j = 0; j < 4; j++)
                    ffma2(acc2[i][j], ap, bp[j]);
            }
        }
        __syncthreads();
    }

    if (isZc) {
        #pragma unroll
        for (int i = 0; i < 8; i++) {
            int r = (i < 4) ? (ty * 4 + i) : (64 + ty * 4 + (i - 4));
            int grow = blockRow + r;
            if (grow < n) {
                float2 p0 = unpack2(acc2[i][0]);
                float2 p1 = unpack2(acc2[i][1]);
                float2 p2 = unpack2(acc2[i][2]);
                float2 p3 = unpack2(acc2[i][3]);
                float4* o = reinterpret_cast<float4*>(outZc + (size_t)grow * FEAT);
                o[tx]      = make_float4(p0.x, p0.y, p1.x, p1.y);
                o[16 + tx] = make_float4(p2.x, p2.y, p3.x, p3.y);
            }
        }
    } else {
        #pragma unroll
        for (int i = 0; i < 8; i++) {
            int r = (i < 4) ? (ty * 4 + i) : (64 + ty * 4 + (i - 4));
            int grow = blockRow + r;
            if (grow < n) {
                float2 p0 = unpack2(acc2[i][0]);
                float2 p1 = unpack2(acc2[i][1]);
                float2 p2 = unpack2(acc2[i][2]);
                float2 p3 = unpack2(acc2[i][3]);
                __half2* o = reinterpret_cast<__half2*>(g_vWn_h + (size_t)grow * FEAT);
                o[tx * 2 + 0]      = __floats2half2_rn(p0.x, p0.y);
                o[tx * 2 + 1]      = __floats2half2_rn(p1.x, p1.y);
                o[32 + tx * 2 + 0] = __floats2half2_rn(p2.x, p2.y);
                o[32 + tx * 2 + 1] = __floats2half2_rn(p3.x, p3.y);
            }
        }
    }
}

// ---------------------------------------------------------------------------
// Kernel 1b: prep — one thread per row. Folds validity mask AND 1/cnt into
// fp16 duplicated edge weights; clamps indices. Output: 40 idx + 40 half2.
// ---------------------------------------------------------------------------
__global__ __launch_bounds__(256) void prep_kernel(
    const int* __restrict__ nh_idx,
    const int* __restrict__ int_idx,
    const float* __restrict__ nh_e,
    const float* __restrict__ int_e,
    int n)
{
    int row = blockIdx.x * blockDim.x + threadIdx.x;
    if (row >= n) return;

    int   idxs[40];
    float es[40];
    #pragma unroll
    for (int q = 0; q < 5; q++) {
        int4   a = __ldg(reinterpret_cast<const int4*>(nh_idx + row * 20) + q);
        float4 e = __ldg(reinterpret_cast<const float4*>(nh_e + row * 20) + q);
        idxs[4*q+0] = a.x; idxs[4*q+1] = a.y; idxs[4*q+2] = a.z; idxs[4*q+3] = a.w;
        es[4*q+0] = e.x; es[4*q+1] = e.y; es[4*q+2] = e.z; es[4*q+3] = e.w;
    }
    #pragma unroll
    for (int q = 0; q < 5; q++) {
        int4   a = __ldg(reinterpret_cast<const int4*>(int_idx + row * 20) + q);
        float4 e = __ldg(reinterpret_cast<const float4*>(int_e + row * 20) + q);
        idxs[20+4*q+0] = a.x; idxs[20+4*q+1] = a.y; idxs[20+4*q+2] = a.z; idxs[20+4*q+3] = a.w;
        es[20+4*q+0] = e.x; es[20+4*q+1] = e.y; es[20+4*q+2] = e.z; es[20+4*q+3] = e.w;
    }

    int cnt = 0;
    #pragma unroll
    for (int j = 0; j < 40; j++)
        cnt += (idxs[j] >= 0) ? 1 : 0;
    float inv = 1.0f / (float)cnt;   // cnt >= 1 guaranteed (nh always valid)

    uint32_t o[80];
    #pragma unroll
    for (int j = 0; j < 40; j++) {
        bool v = idxs[j] >= 0;
        o[j] = (uint32_t)(v ? idxs[j] : 0);
        __half2 h = __float2half2_rn(v ? es[j] * inv : 0.0f);
        o[40 + j] = *reinterpret_cast<uint32_t*>(&h);
    }
    uint4* dst = reinterpret_cast<uint4*>(g_prep + (size_t)row * 80);
    #pragma unroll
    for (int q = 0; q < 20; q++)
        dst[q] = make_uint4(o[4*q], o[4*q+1], o[4*q+2], o[4*q+3]);
}

// ---------------------------------------------------------------------------
// Kernel 2: gather with HFMA2 fp16 accumulation.
// One warp per row; lane owns cols [lane*4, lane*4+4) = one uint2 (4 halves).
// Per neighbor: addr + LDG.64 + 2x HFMA2. Four accumulator chains (<=20 adds
// each), merged + converted to fp32 at the end.
// ---------------------------------------------------------------------------
__global__ __launch_bounds__(256, 6) void gather_kernel(
    float* __restrict__ out,
    const float* __restrict__ bv,
    int n)
{
    int gwarp = (blockIdx.x * blockDim.x + threadIdx.x) >> 5;
    int lane  = threadIdx.x & 31;
    if (gwarp >= n) return;
    int row = gwarp;

    const uint2* vW2 = reinterpret_cast<const uint2*>(g_vWn_h);
    const uint32_t* P = g_prep + (size_t)row * 80;

    __half2 accA0 = __float2half2_rn(0.f), accA1 = __float2half2_rn(0.f);
    __half2 accB0 = __float2half2_rn(0.f), accB1 = __float2half2_rn(0.f);

    #pragma unroll
    for (int h = 0; h < 2; h++) {
        // load 20 idx + 20 half2 edges for this half (broadcast, L1-resident)
        uint32_t idxv[20], e2v[20];
        #pragma unroll
        for (int q = 0; q < 5; q++) {
            uint4 a = __ldg(reinterpret_cast<const uint4*>(P + h * 20) + q);
            idxv[4*q+0] = a.x; idxv[4*q+1] = a.y; idxv[4*q+2] = a.z; idxv[4*q+3] = a.w;
            uint4 b = __ldg(reinterpret_cast<const uint4*>(P + 40 + h * 20) + q);
            e2v[4*q+0] = b.x; e2v[4*q+1] = b.y; e2v[4*q+2] = b.z; e2v[4*q+3] = b.w;
        }
        #pragma unroll
        for (int j = 0; j < 20; j += 2) {
            uint2 v0 = __ldg(vW2 + (size_t)idxv[j]   * 32 + lane);
            uint2 v1 = __ldg(vW2 + (size_t)idxv[j+1] * 32 + lane);
            __half2 e0 = *reinterpret_cast<__half2*>(&e2v[j]);
            __half2 e1 = *reinterpret_cast<__half2*>(&e2v[j+1]);
            accA0 = __hfma2(*reinterpret_cast<__half2*>(&v0.x), e0, accA0);
            accB0 = __hfma2(*reinterpret_cast<__half2*>(&v0.y), e0, accB0);
            accA1 = __hfma2(*reinterpret_cast<__half2*>(&v1.x), e1, accA1);
            accB1 = __hfma2(*reinterpret_cast<__half2*>(&v1.y), e1, accB1);
        }
    }

    float2 fa = __half22float2(__hadd2(accA0, accA1));
    float2 fb = __half22float2(__hadd2(accB0, accB1));

    float4 zc = reinterpret_cast<const float4*>(out)[(size_t)row * 32 + lane];
    float4 b  = __ldg(reinterpret_cast<const float4*>(bv) + lane);
    float4 z;
    z.x = fmaxf(zc.x + fa.x + b.x, 0.f);
    z.y = fmaxf(zc.y + fa.y + b.y, 0.f);
    z.z = fmaxf(zc.z + fb.x + b.z, 0.f);
    z.w = fmaxf(zc.w + fb.y + b.w, 0.f);
    reinterpret_cast<float4*>(out)[(size_t)row * 32 + lane] = z;
}

// ---------------------------------------------------------------------------
extern "C" void kernel_launch(void* const* d_in, const int* in_sizes, int n_in,
                              void* d_out, int out_size) {
    const float* vertices    = (const float*)d_in[0];
    const int*   nh_indices  = (const int*)  d_in[1];
    const int*   int_indices = (const int*)  d_in[2];
    const float* nh_edges    = (const float*)d_in[3];
    const float* int_edges   = (const float*)d_in[4];
    const float* Wvc         = (const float*)d_in[5];
    const float* Wvn         = (const float*)d_in[6];
    const float* bv          = (const float*)d_in[7];
    float* out = (float*)d_out;

    int n = in_sizes[0] / FEAT;   // 50000

    dim3 g1((n + BM - 1) / BM, 2);
    gemm_kernel<<<g1, 256>>>(vertices, Wvc, Wvn, out, n);

    int gp = (n + 255) / 256;
    prep_kernel<<<gp, 256>>>(nh_indices, int_indices, nh_edges, int_edges, n);

    int warps_per_block = 256 / 32;
    int g2 = (n + warps_per_block - 1) / warps_per_block;
    gather_kernel<<<g2, 256>>>(out, bv, n);
}

// round 9
// speedup vs baseline: 1.5639x; 1.0596x over previous
#include <cuda_runtime.h>
#include <cuda_fp16.h>
#include <cstdint>
#include <mma.h>

using namespace nvcuda;

#define FEAT 128
#define BM 128
#define BN 128
#define BK 16
#define PAD_BM 132
#define NPAD 50176

typedef unsigned long long ull;

// scratch for v @ Wvn in fp16  (N padded to 50176 rows)
__device__ __half g_vWn_h[NPAD * FEAT];
// prepped neighbor data, TRANSPOSED for coalescing:
// g_pidx[q][row] = 4 clamped indices; g_pe2[q][row] = 4 x half2(e/cnt)
__device__ uint4 g_pidx[10 * NPAD];
__device__ uint4 g_pe2[10 * NPAD];

// ---------------------------------------------------------------------------
// Packed dual-fp32 FMA (Blackwell family-wide, SASS FFMA2).
// ---------------------------------------------------------------------------
__device__ __forceinline__ unsigned long long pack2(float x, float y) {
    unsigned long long r;
    asm("mov.b64 %0, {%1, %2};" : "=l"(r) : "f"(x), "f"(y));
    return r;
}
__device__ __forceinline__ float2 unpack2(unsigned long long v) {
    float2 f;
    asm("mov.b64 {%0, %1}, %2;" : "=f"(f.x), "=f"(f.y) : "l"(v));
    return f;
}
__device__ __forceinline__ void ffma2(unsigned long long& acc,
                                      unsigned long long a,
                                      unsigned long long b) {
    asm("fma.rn.f32x2 %0, %1, %2, %0;" : "+l"(acc) : "l"(a), "l"(b));
}

// ---------------------------------------------------------------------------
// Kernel 1: Zc = A @ Wvc in exact fp32 (R5 FFMA2 GEMM, single output).
// ---------------------------------------------------------------------------
__global__ __launch_bounds__(256) void gemm_zc_kernel(
    const float* __restrict__ A,
    const float* __restrict__ W,
    float* __restrict__ outZc,
    int n)
{
    __shared__ float As[BK][PAD_BM];
    __shared__ float Bs[BK][BN];

    int tid = threadIdx.x;
    int tx = tid & 15;
    int ty = tid >> 4;
    int blockRow = blockIdx.x * BM;

    ull acc2[8][4];
    #pragma unroll
    for (int i = 0; i < 8; i++)
        #pragma unroll
        for (int j = 0; j < 4; j++)
            acc2[i][j] = 0ull;

    for (int k0 = 0; k0 < FEAT; k0 += BK) {
        #pragma unroll
        for (int i = 0; i < 2; i++) {
            int f4  = tid + i * 256;
            int row = f4 >> 2;
            int q   = f4 & 3;
            int grow = blockRow + row;
            float4 v = make_float4(0.f, 0.f, 0.f, 0.f);
            if (grow < n)
                v = reinterpret_cast<const float4*>(A)[grow * (FEAT / 4) + (k0 >> 2) + q];
            As[4 * q + 0][row] = v.x;
            As[4 * q + 1][row] = v.y;
            As[4 * q + 2][row] = v.z;
            As[4 * q + 3][row] = v.w;
        }
        #pragma unroll
        for (int i = 0; i < 2; i++) {
            int f4 = tid + i * 256;
            int kk = f4 >> 5;
            int c4 = f4 & 31;
            reinterpret_cast<float4*>(&Bs[kk][0])[c4] =
                reinterpret_cast<const float4*>(W)[(k0 + kk) * (FEAT / 4) + c4];
        }
        __syncthreads();

        #pragma unroll
        for (int kk = 0; kk < BK; kk++) {
            float4 a0 = *reinterpret_cast<const float4*>(&As[kk][ty * 4]);
            float4 a1 = *reinterpret_cast<const float4*>(&As[kk][64 + ty * 4]);
            float4 b0 = *reinterpret_cast<const float4*>(&Bs[kk][tx * 4]);
            float4 b1 = *reinterpret_cast<const float4*>(&Bs[kk][64 + tx * 4]);
            ull bp[4] = {
                pack2(b0.x, b0.y), pack2(b0.z, b0.w),
                pack2(b1.x, b1.y), pack2(b1.z, b1.w)
            };
            float a[8] = {a0.x, a0.y, a0.z, a0.w, a1.x, a1.y, a1.z, a1.w};
            #pragma unroll
            for (int i = 0; i < 8; i++) {
                ull ap = pack2(a[i], a[i]);
                #pragma unroll
                for (int j = 0; j < 4; j++)
                    ffma2(acc2[i][j], ap, bp[j]);
            }
        }
        __syncthreads();
    }

    #pragma unroll
    for (int i = 0; i < 8; i++) {
        int r = (i < 4) ? (ty * 4 + i) : (64 + ty * 4 + (i - 4));
        int grow = blockRow + r;
        if (grow < n) {
            float2 p0 = unpack2(acc2[i][0]);
            float2 p1 = unpack2(acc2[i][1]);
            float2 p2 = unpack2(acc2[i][2]);
            float2 p3 = unpack2(acc2[i][3]);
            float4* o = reinterpret_cast<float4*>(outZc + (size_t)grow * FEAT);
            o[tx]      = make_float4(p0.x, p0.y, p1.x, p1.y);
            o[16 + tx] = make_float4(p2.x, p2.y, p3.x, p3.y);
        }
    }
}

// ---------------------------------------------------------------------------
// Kernel 2: vWn = A @ Wvn via HMMA (wmma, fp16 in / fp32 accum / fp16 out).
// 128x128 CTA tile, whole K=128 resident in smem; 8 warps, each 32x64.
// ---------------------------------------------------------------------------
#define LDH 136   // half stride (multiple of 8), padded vs 128

__global__ __launch_bounds__(256, 2) void wmma_vwn_kernel(
    const float* __restrict__ A,
    const float* __restrict__ W,
    int n)
{
    extern __shared__ __half sh[];
    __half* Ah = sh;                   // [128][LDH]
    __half* Wh = sh + 128 * LDH;       // [128][LDH]

    int tid = threadIdx.x;
    int blockRow = blockIdx.x * 128;

    // load + convert A tile (guarded) and full W (unguarded)
    for (int i = tid; i < 128 * 32; i += 256) {
        int row = i >> 5, q = i & 31;
        int grow = blockRow + row;
        float4 v = make_float4(0.f, 0.f, 0.f, 0.f);
        if (grow < n) v = reinterpret_cast<const float4*>(A)[grow * 32 + q];
        __half2* dst = reinterpret_cast<__half2*>(&Ah[row * LDH + q * 4]);
        dst[0] = __floats2half2_rn(v.x, v.y);
        dst[1] = __floats2half2_rn(v.z, v.w);
    }
    for (int i = tid; i < 128 * 32; i += 256) {
        int row = i >> 5, q = i & 31;
        float4 v = reinterpret_cast<const float4*>(W)[row * 32 + q];
        __half2* dst = reinterpret_cast<__half2*>(&Wh[row * LDH + q * 4]);
        dst[0] = __floats2half2_rn(v.x, v.y);
        dst[1] = __floats2half2_rn(v.z, v.w);
    }
    __syncthreads();

    int w = tid >> 5;
    int m0 = (w & 3) * 32;      // 4 row groups of 32
    int n0 = (w >> 2) * 64;     // 2 col groups of 64

    wmma::fragment<wmma::accumulator, 16, 16, 16, float> acc[2][4];
    #pragma unroll
    for (int i = 0; i < 2; i++)
        #pragma unroll
        for (int j = 0; j < 4; j++)
            wmma::fill_fragment(acc[i][j], 0.0f);

    #pragma unroll
    for (int k = 0; k < 128; k += 16) {
        wmma::fragment<wmma::matrix_a, 16, 16, 16, __half, wmma::row_major> fa[2];
        #pragma unroll
        for (int i = 0; i < 2; i++)
            wmma::load_matrix_sync(fa[i], &Ah[(m0 + 16 * i) * LDH + k], LDH);
        #pragma unroll
        for (int j = 0; j < 4; j++) {
            wmma::fragment<wmma::matrix_b, 16, 16, 16, __half, wmma::row_major> fb;
            wmma::load_matrix_sync(fb, &Wh[k * LDH + n0 + 16 * j], LDH);
            #pragma unroll
            for (int i = 0; i < 2; i++)
                wmma::mma_sync(acc[i][j], fa[i], fb, acc[i][j]);
        }
    }

    // convert accumulators to half, store straight to padded global buffer
    #pragma unroll
    for (int i = 0; i < 2; i++)
        #pragma unroll
        for (int j = 0; j < 4; j++) {
            wmma::fragment<wmma::accumulator, 16, 16, 16, __half> ch;
            #pragma unroll
            for (int t = 0; t < ch.num_elements; t++)
                ch.x[t] = __float2half(acc[i][j].x[t]);
            __half* dst = g_vWn_h + (size_t)(blockRow + m0 + 16 * i) * FEAT + n0 + 16 * j;
            wmma::store_matrix_sync(dst, ch, FEAT, wmma::mem_row_major);
        }
}

// ---------------------------------------------------------------------------
// Kernel 3: prep — one thread per row; COALESCED transposed output.
// ---------------------------------------------------------------------------
__global__ __launch_bounds__(256) void prep_kernel(
    const int* __restrict__ nh_idx,
    const int* __restrict__ int_idx,
    const float* __restrict__ nh_e,
    const float* __restrict__ int_e,
    int n)
{
    int row = blockIdx.x * blockDim.x + threadIdx.x;
    if (row >= n) return;

    int   idxs[40];
    float es[40];
    #pragma unroll
    for (int q = 0; q < 5; q++) {
        int4   a = __ldg(reinterpret_cast<const int4*>(nh_idx + row * 20) + q);
        float4 e = __ldg(reinterpret_cast<const float4*>(nh_e + row * 20) + q);
        idxs[4*q+0] = a.x; idxs[4*q+1] = a.y; idxs[4*q+2] = a.z; idxs[4*q+3] = a.w;
        es[4*q+0] = e.x; es[4*q+1] = e.y; es[4*q+2] = e.z; es[4*q+3] = e.w;
    }
    #pragma unroll
    for (int q = 0; q < 5; q++) {
        int4   a = __ldg(reinterpret_cast<const int4*>(int_idx + row * 20) + q);
        float4 e = __ldg(reinterpret_cast<const float4*>(int_e + row * 20) + q);
        idxs[20+4*q+0] = a.x; idxs[20+4*q+1] = a.y; idxs[20+4*q+2] = a.z; idxs[20+4*q+3] = a.w;
        es[20+4*q+0] = e.x; es[20+4*q+1] = e.y; es[20+4*q+2] = e.z; es[20+4*q+3] = e.w;
    }

    int cnt = 0;
    #pragma unroll
    for (int j = 0; j < 40; j++)
        cnt += (idxs[j] >= 0) ? 1 : 0;
    float inv = 1.0f / (float)cnt;

    #pragma unroll
    for (int q = 0; q < 10; q++) {
        uint32_t oi[4], oe[4];
        #pragma unroll
        for (int t = 0; t < 4; t++) {
            int j = 4 * q + t;
            bool v = idxs[j] >= 0;
            oi[t] = (uint32_t)(v ? idxs[j] : 0);
            __half2 h = __float2half2_rn(v ? es[j] * inv : 0.0f);
            oe[t] = *reinterpret_cast<uint32_t*>(&h);
        }
        g_pidx[q * NPAD + row] = make_uint4(oi[0], oi[1], oi[2], oi[3]);
        g_pe2[q * NPAD + row]  = make_uint4(oe[0], oe[1], oe[2], oe[3]);
    }
}

// ---------------------------------------------------------------------------
// Kernel 4: gather with HFMA2 fp16 accumulation (transposed prep reads).
// ---------------------------------------------------------------------------
__global__ __launch_bounds__(256, 4) void gather_kernel(
    float* __restrict__ out,
    const float* __restrict__ bv,
    int n)
{
    int gwarp = (blockIdx.x * blockDim.x + threadIdx.x) >> 5;
    int lane  = threadIdx.x & 31;
    if (gwarp >= n) return;
    int row = gwarp;

    const uint2* vW2 = reinterpret_cast<const uint2*>(g_vWn_h);

    __half2 accA0 = __float2half2_rn(0.f), accA1 = __float2half2_rn(0.f);
    __half2 accB0 = __float2half2_rn(0.f), accB1 = __float2half2_rn(0.f);

    #pragma unroll
    for (int h = 0; h < 2; h++) {
        uint32_t idxv[20], e2v[20];
        #pragma unroll
        for (int q = 0; q < 5; q++) {
            uint4 a = __ldg(&g_pidx[(h * 5 + q) * NPAD + row]);   // broadcast
            idxv[4*q+0] = a.x; idxv[4*q+1] = a.y; idxv[4*q+2] = a.z; idxv[4*q+3] = a.w;
            uint4 b = __ldg(&g_pe2[(h * 5 + q) * NPAD + row]);    // broadcast
            e2v[4*q+0] = b.x; e2v[4*q+1] = b.y; e2v[4*q+2] = b.z; e2v[4*q+3] = b.w;
        }
        #pragma unroll
        for (int j = 0; j < 20; j += 2) {
            uint2 v0 = __ldg(vW2 + (size_t)idxv[j]   * 32 + lane);
            uint2 v1 = __ldg(vW2 + (size_t)idxv[j+1] * 32 + lane);
            __half2 e0 = *reinterpret_cast<__half2*>(&e2v[j]);
            __half2 e1 = *reinterpret_cast<__half2*>(&e2v[j+1]);
            accA0 = __hfma2(*reinterpret_cast<__half2*>(&v0.x), e0, accA0);
            accB0 = __hfma2(*reinterpret_cast<__half2*>(&v0.y), e0, accB0);
            accA1 = __hfma2(*reinterpret_cast<__half2*>(&v1.x), e1, accA1);
            accB1 = __hfma2(*reinterpret_cast<__half2*>(&v1.y), e1, accB1);
        }
    }

    float2 fa = __half22float2(__hadd2(accA0, accA1));
    float2 fb = __half22float2(__hadd2(accB0, accB1));

    float4 zc = reinterpret_cast<const float4*>(out)[(size_t)row * 32 + lane];
    float4 b  = __ldg(reinterpret_cast<const float4*>(bv) + lane);
    float4 z;
    z.x = fmaxf(zc.x + fa.x + b.x, 0.f);
    z.y = fmaxf(zc.y + fa.y + b.y, 0.f);
    z.z = fmaxf(zc.z + fb.x + b.z, 0.f);
    z.w = fmaxf(zc.w + fb.y + b.w, 0.f);
    reinterpret_cast<float4*>(out)[(size_t)row * 32 + lane] = z;
}

// ---------------------------------------------------------------------------
extern "C" void kernel_launch(void* const* d_in, const int* in_sizes, int n_in,
                              void* d_out, int out_size) {
    const float* vertices    = (const float*)d_in[0];
    const int*   nh_indices  = (const int*)  d_in[1];
    const int*   int_indices = (const int*)  d_in[2];
    const float* nh_edges    = (const float*)d_in[3];
    const float* int_edges   = (const float*)d_in[4];
    const float* Wvc         = (const float*)d_in[5];
    const float* Wvn         = (const float*)d_in[6];
    const float* bv          = (const float*)d_in[7];
    float* out = (float*)d_out;

    int n = in_sizes[0] / FEAT;   // 50000
    int nblk = (n + 127) / 128;   // 391

    static const size_t wmma_smem = 2 * 128 * LDH * sizeof(__half);  // 69632
    cudaFuncSetAttribute(wmma_vwn_kernel,
                         cudaFuncAttributeMaxDynamicSharedMemorySize, (int)wmma_smem);

    gemm_zc_kernel<<<nblk, 256>>>(vertices, Wvc, out, n);
    wmma_vwn_kernel<<<nblk, 256, wmma_smem>>>(vertices, Wvn, n);

    int gp = (n + 255) / 256;
    prep_kernel<<<gp, 256>>>(nh_indices, int_indices, nh_edges, int_edges, n);

    int g2 = (n + 7) / 8;
    gather_kernel<<<g2, 256>>>(out, bv, n);
}